// round 16
// baseline (speedup 1.0000x reference)
#include <cuda_runtime.h>
#include <cuda.h>
#include <cuda_fp16.h>
#include <cstdint>

#if !defined(__CUDA_ARCH__) || defined(__CUDA_ARCH_FEAT_SM103_ALL)
#define TC_OK 1
#else
#define TC_OK 0
#endif

// ---------------- problem constants ----------------------------------------
#define DIMN   1024
#define SEQ    2048
#define BATCH  2
#define NH     16
#define HDIM   64
#define MROWS  (BATCH*SEQ)              // 4096
#define MASKW  (SEQ/32)                 // 64 words per (b,q) row
#define QSCALE 0.045084220f             // (1/32)*log2(e): p = ex2(S)
#define NWORK  512                      // attention work items
#define NPCTA  296                      // persistent CTAs (148 SMs x 2)

// ---------------- scratch (static device globals) ---------------------------
__device__ __align__(1024) __half g_Qh [(size_t)MROWS*DIMN];
__device__ __align__(1024) __half g_Kh [(size_t)MROWS*DIMN];
__device__ __align__(1024) __half g_Vth[(size_t)BATCH*DIMN*SEQ]; // [b*1024+d][s]
__device__ __align__(1024) __half g_AOh[(size_t)MROWS*DIMN];
__device__ __align__(1024) __half g_qA[(size_t)MROWS*DIMN];
__device__ __align__(1024) __half g_kA[(size_t)MROWS*DIMN];
__device__ __align__(1024) __half g_vA[(size_t)MROWS*DIMN];
__device__ __align__(1024) __half g_wqA[(size_t)DIMN*DIMN];
__device__ __align__(1024) __half g_wkA[(size_t)DIMN*DIMN];
__device__ __align__(1024) __half g_wvA[(size_t)DIMN*DIMN];
__device__ __align__(1024) __half g_woA[(size_t)DIMN*DIMN];
__device__ unsigned g_maskbits[(size_t)BATCH*SEQ*MASKW];  // 1 = masked
__device__ unsigned g_flags = 0;

// ---------------- PTX helpers ----------------------------------------------
__device__ __forceinline__ uint32_t smem_to_u32(const void* smem_ptr) {
    uint32_t addr;
    asm("{ .reg .u64 tmp; cvta.to.shared.u64 tmp, %1; cvt.u32.u64 %0, tmp; }"
        : "=r"(addr) : "l"(smem_ptr));
    return addr;
}
__device__ __forceinline__ void fence_proxy_async() {
    asm volatile("fence.proxy.async;" ::: "memory");
}
__device__ __forceinline__ void fence_proxy_async_shared() {
    asm volatile("fence.proxy.async.shared::cta;" ::: "memory");
}
__device__ __forceinline__ uint32_t pack_f16x2(float lo, float hi) {
    uint32_t d;
    asm("cvt.rn.f16x2.f32 %0, %1, %2;" : "=r"(d) : "f"(hi), "f"(lo));
    return d;
}
__device__ __forceinline__ float ex2f(float x) {
    float r;
    asm("ex2.approx.f32 %0, %1;" : "=f"(r) : "f"(x));
    return r;
}

#define MBARRIER_INIT(mbar, count) \
    asm volatile("mbarrier.init.shared.b64 [%0], %1;" \
        :: "r"((uint32_t)(mbar)), "r"((uint32_t)(count)) : "memory")

#define MBARRIER_ARRIVE(mbar) \
    asm volatile("mbarrier.arrive.shared.b64 _, [%0];" \
        :: "r"((uint32_t)(mbar)) : "memory")

#define MBARRIER_EXPECT_TX(mbar, tx_bytes) \
    asm volatile("mbarrier.arrive.expect_tx.shared.b64 _, [%0], %1;" \
        :: "r"((uint32_t)(mbar)), "r"((uint32_t)(tx_bytes)) : "memory")

#define MBARRIER_WAIT_PARITY(mbar_smem_addr, phase_parity) do { \
    uint32_t _mbar = (uint32_t)(mbar_smem_addr); \
    uint32_t _parity = (uint32_t)(phase_parity); \
    uint32_t _done; \
    asm volatile( \
        "{\n\t.reg .pred p;\n\t" \
        "mbarrier.try_wait.parity.acquire.cta.shared::cta.b64 p, [%1], %2;\n\t" \
        "selp.b32 %0, 1, 0, p;\n\t}" \
        : "=r"(_done) : "r"(_mbar), "r"(_parity) : "memory"); \
    if (!_done) { \
        asm volatile( \
            "{\n\t.reg .pred P1;\n\t" \
            "WAIT_LOOP_%=:\n\t" \
            "mbarrier.try_wait.parity.acquire.cta.shared::cta.b64 P1, [%0], %1, 0x989680;\n\t" \
            "@P1 bra.uni WAIT_DONE_%=;\n\t" \
            "bra.uni WAIT_LOOP_%=;\n\t" \
            "WAIT_DONE_%=:\n\t}" \
            :: "r"(_mbar), "r"(_parity) : "memory"); \
    } \
} while(0)

#define TCGEN05_ALLOC(smem_result_addr, nCols) \
    asm volatile("tcgen05.alloc.cta_group::1.sync.aligned.shared::cta.b32 [%0], %1;" \
        :: "r"((uint32_t)(smem_result_addr)), "r"((uint32_t)(nCols)) : "memory")
#define TCGEN05_DEALLOC(tmem_addr, nCols) \
    asm volatile("tcgen05.dealloc.cta_group::1.sync.aligned.b32 %0, %1;" \
        :: "r"(tmem_addr), "r"(nCols))
#define TCGEN05_RELINQUISH_ALLOC_PERMIT() \
    asm volatile("tcgen05.relinquish_alloc_permit.cta_group::1.sync.aligned;")
#define TCGEN05_COMMIT(mbar) \
    asm volatile("tcgen05.commit.cta_group::1.mbarrier::arrive::one.shared::cluster.b64 [%0];" \
        :: "r"((uint32_t)(mbar)) : "memory")
#define TCGEN05_WAIT_LD() \
    asm volatile("tcgen05.wait::ld.sync.aligned;" ::: "memory")
#define TCGEN05_FENCE_BEFORE() \
    asm volatile("tcgen05.fence::before_thread_sync;" ::: "memory")
#define TCGEN05_FENCE_AFTER() \
    asm volatile("tcgen05.fence::after_thread_sync;" ::: "memory")

#define TCGEN05_LD_32X32B_X32(r, tmem_addr) \
    asm volatile( \
        "tcgen05.ld.sync.aligned.32x32b.x32.b32 " \
        "{%0, %1, %2, %3, %4, %5, %6, %7, " \
        " %8, %9, %10, %11, %12, %13, %14, %15, " \
        " %16, %17, %18, %19, %20, %21, %22, %23, " \
        " %24, %25, %26, %27, %28, %29, %30, %31}, [%32];" \
        : "=r"((r)[0]),  "=r"((r)[1]),  "=r"((r)[2]),  "=r"((r)[3]), \
          "=r"((r)[4]),  "=r"((r)[5]),  "=r"((r)[6]),  "=r"((r)[7]), \
          "=r"((r)[8]),  "=r"((r)[9]),  "=r"((r)[10]), "=r"((r)[11]), \
          "=r"((r)[12]), "=r"((r)[13]), "=r"((r)[14]), "=r"((r)[15]), \
          "=r"((r)[16]), "=r"((r)[17]), "=r"((r)[18]), "=r"((r)[19]), \
          "=r"((r)[20]), "=r"((r)[21]), "=r"((r)[22]), "=r"((r)[23]), \
          "=r"((r)[24]), "=r"((r)[25]), "=r"((r)[26]), "=r"((r)[27]), \
          "=r"((r)[28]), "=r"((r)[29]), "=r"((r)[30]), "=r"((r)[31]) \
        : "r"(tmem_addr))

static constexpr uint64_t SMEM_DESC_BASE_SW128 =
    (uint64_t(2)  << 61) | (uint64_t(1) << 46) | (uint64_t(64) << 32) | (uint64_t(1) << 16);
#define MAKE_SMEM_DESC(base_addr) \
    (SMEM_DESC_BASE_SW128 | ((uint64_t)((base_addr) >> 4) & 0x3FFF))

__device__ __forceinline__ void tma_load_2d_(
    uint32_t smem_addr, const void* tensor_map,
    int32_t cx, int32_t cy, uint32_t mbar)
{
    asm volatile(
        "cp.async.bulk.tensor.2d.shared::cta.global.tile.mbarrier::complete_tx::bytes "
        "[%0], [%1, {%2, %3}], [%4];"
        :: "r"(smem_addr), "l"(tensor_map), "r"(cx), "r"(cy), "r"(mbar)
        : "memory");
}

__device__ __forceinline__ void mma_f16_ss(
    uint32_t d_tmem, uint64_t a_desc, uint64_t b_desc, uint32_t idesc, bool acc)
{
#if TC_OK
    uint32_t e = acc ? 1u : 0u;
    asm volatile(
        "{\n\t.reg .pred p;\n\t"
        "setp.ne.u32 p, %4, 0;\n\t"
        "tcgen05.mma.cta_group::1.kind::f16 [%0], %1, %2, %3, p;\n\t}"
        :: "r"(d_tmem), "l"(a_desc), "l"(b_desc), "r"(idesc), "r"(e)
        : "memory");
#endif
}

// ---------------- prep: fp16 rounding (z 0-6) + mask sniff (z 7) ------------
__global__ __launch_bounds__(256) void prep_all(
    const float* __restrict__ q, const float* __restrict__ k, const float* __restrict__ v,
    const float* __restrict__ wq, const float* __restrict__ wk,
    const float* __restrict__ wv, const float* __restrict__ wo,
    const unsigned* __restrict__ mask)
{
    const int z = blockIdx.y;
    if (z == 7) {
        unsigned vv = mask[blockIdx.x * 256 + threadIdx.x];
        unsigned f = 0;
        if (vv != 0u && vv != 1u) {
            if (vv == 0x3F800000u)                     f = 2u;
            else if (vv == 0x3F80u || vv == 0x3F803F80u) f = 4u;
            else                                        f = 1u;
        }
        f = __reduce_or_sync(0xFFFFFFFFu, f);
        if ((threadIdx.x & 31) == 0 && f) atomicOr(&g_flags, f);
        return;
    }
    const float* in; __half* out;
    switch (z) {
        case 0: in = q;  out = g_qA;  break;
        case 1: in = k;  out = g_kA;  break;
        case 2: in = v;  out = g_vA;  break;
        case 3: in = wq; out = g_wqA; break;
        case 4: in = wk; out = g_wkA; break;
        case 5: in = wv; out = g_wvA; break;
        default: in = wo; out = g_woA; break;
    }
    if (z >= 3 && blockIdx.x >= 1024) return;
    int i = (blockIdx.x * 256 + threadIdx.x) * 4;
    float4 t = *(const float4*)(in + i);
    uint2 w;
    w.x = pack_f16x2(t.x, t.y);
    w.y = pack_f16x2(t.z, t.w);
    *(uint2*)(out + i) = w;
}

__global__ void pack_mask(const void* __restrict__ mask)
{
    int w = blockIdx.x * blockDim.x + threadIdx.x;
    const int NW = BATCH * SEQ * MASKW;
    if (w >= NW) return;
    unsigned ff = g_flags;
    int mode = (ff & 4u) ? 3 : (ff & 2u) ? 1 : (ff & 1u) ? 2 : 0;
    size_t base = (size_t)w * 32;
    unsigned bits = 0;
    if (mode == 0) {
        const int* p = (const int*)mask;
        #pragma unroll
        for (int j = 0; j < 32; j++) if (p[base + j] != 0) bits |= 1u << j;
    } else if (mode == 1) {
        const float* p = (const float*)mask;
        #pragma unroll
        for (int j = 0; j < 32; j++) if (p[base + j] != 0.0f) bits |= 1u << j;
    } else if (mode == 2) {
        const unsigned char* p = (const unsigned char*)mask;
        #pragma unroll
        for (int j = 0; j < 32; j++) if (p[base + j] != 0) bits |= 1u << j;
    } else {
        const unsigned short* p = (const unsigned short*)mask;
        #pragma unroll
        for (int j = 0; j < 32; j++) if (p[base + j] != 0) bits |= 1u << j;
    }
    g_maskbits[w] = bits;
}

// ---------------- tcgen05 fp16 GEMM core ------------------------------------
#define G_NSTAGE 3
#define G_KSTEP  64
#define G_KITERS (DIMN / G_KSTEP)           // 16
#define G_STAGE_A_BYTES (128 * 128)
#define G_STAGE_B_BYTES (256 * 128)
#define G_STAGE_BYTES   (G_STAGE_A_BYTES + G_STAGE_B_BYTES)
#define G_SMEM_STAGE0   2048
#define G_SMEM_TOTAL    (G_SMEM_STAGE0 + G_NSTAGE * G_STAGE_BYTES)   // 149504
#define G_IDESC 0x8400010u      // f16, M=128, N=256, fp32 acc

__device__ __forceinline__ void gemm_core(
    const CUtensorMap* mapA, const CUtensorMap* mapW,
    const float* __restrict__ bias, float* __restrict__ C,
    __half* __restrict__ C16, int mode, float oscale)
{
#if TC_OK
    extern __shared__ __align__(1024) char smem[];
    const uint32_t sb = smem_to_u32(smem);
    const uint32_t fullb  = sb;
    const uint32_t emptyb = sb + 8;
    const uint32_t doneb  = sb + 48;
    const uint32_t tptr   = sb + 64;
    float* sbias = (float*)(smem + 1024);

    const int tid = threadIdx.x, wid = tid >> 5, lid = tid & 31;
    const int bx = blockIdx.x, by = blockIdx.y;

    if (tid == 0) {
        #pragma unroll
        for (int s = 0; s < G_NSTAGE; s++) {
            MBARRIER_INIT(fullb  + 16 * s, 1);
            MBARRIER_INIT(emptyb + 16 * s, 1);
        }
        MBARRIER_INIT(doneb, 1);
        fence_proxy_async();
    }
    if (wid == 0) {
        TCGEN05_ALLOC(tptr, 256);
        TCGEN05_RELINQUISH_ALLOC_PERMIT();
    }
    sbias[tid]       = bias[bx * 256 + tid];
    sbias[tid + 128] = bias[bx * 256 + tid + 128];
    __syncthreads();

    uint32_t tmem;
    asm volatile("ld.shared.b32 %0, [%1];" : "=r"(tmem) : "r"(tptr));

    if (tid == 0) {
        int st = 0, ph = 1;
        for (int s = 0; s < G_KITERS; s++) {
            MBARRIER_WAIT_PARITY(emptyb + 16 * st, ph);
            MBARRIER_EXPECT_TX(fullb + 16 * st, G_STAGE_BYTES);
            uint32_t sa = sb + G_SMEM_STAGE0 + st * G_STAGE_BYTES;
            tma_load_2d_(sa,                   mapA, s * G_KSTEP, by * 128, fullb + 16 * st);
            tma_load_2d_(sa + G_STAGE_A_BYTES, mapW, s * G_KSTEP, bx * 256, fullb + 16 * st);
            if (++st == G_NSTAGE) { st = 0; ph ^= 1; }
        }
    } else if (tid == 32) {
        int st = 0, ph = 0;
        for (int s = 0; s < G_KITERS; s++) {
            MBARRIER_WAIT_PARITY(fullb + 16 * st, ph);
            uint32_t sa = sb + G_SMEM_STAGE0 + st * G_STAGE_BYTES;
            uint64_t ad = MAKE_SMEM_DESC(sa);
            uint64_t bd = MAKE_SMEM_DESC(sa + G_STAGE_A_BYTES);
            #pragma unroll
            for (int k = 0; k < 4; k++)
                mma_f16_ss(tmem, ad + k * 2, bd + k * 2, G_IDESC, (s > 0) || (k > 0));
            TCGEN05_COMMIT(emptyb + 16 * st);
            if (++st == G_NSTAGE) { st = 0; ph ^= 1; }
        }
        TCGEN05_COMMIT(doneb);
    }

    MBARRIER_WAIT_PARITY(doneb, 0);
    TCGEN05_FENCE_AFTER();

    const int m = by * 128 + wid * 32 + lid;
    if (mode == 2) {
        const int bb = m >> 11, s = m & (SEQ - 1);
        __half* base = g_Vth + (size_t)bb * DIMN * SEQ + s;
        #pragma unroll
        for (int ch = 0; ch < 8; ch++) {
            uint32_t r[32];
            TCGEN05_LD_32X32B_X32(r, tmem + ch * 32);
            TCGEN05_WAIT_LD();
            #pragma unroll
            for (int j = 0; j < 32; j++) {
                int n = bx * 256 + ch * 32 + j;
                base[(size_t)n * SEQ] =
                    __float2half_rn(__uint_as_float(r[j]) + sbias[ch * 32 + j]);
            }
        }
    } else if (mode == 1) {
        __half* crow = C16 + (size_t)m * DIMN + bx * 256;
        #pragma unroll
        for (int ch = 0; ch < 8; ch++) {
            uint32_t r[32];
            TCGEN05_LD_32X32B_X32(r, tmem + ch * 32);
            TCGEN05_WAIT_LD();
            #pragma unroll
            for (int j = 0; j < 32; j += 8) {
                float v[8];
                #pragma unroll
                for (int t = 0; t < 8; t++)
                    v[t] = (__uint_as_float(r[j + t]) + sbias[ch * 32 + j + t]) * oscale;
                uint4 w;
                w.x = pack_f16x2(v[0], v[1]);
                w.y = pack_f16x2(v[2], v[3]);
                w.z = pack_f16x2(v[4], v[5]);
                w.w = pack_f16x2(v[6], v[7]);
                *(uint4*)(crow + ch * 32 + j) = w;
            }
        }
    } else {
        float* crow = C + (size_t)m * DIMN + bx * 256;
        #pragma unroll
        for (int ch = 0; ch < 8; ch++) {
            uint32_t r[32];
            TCGEN05_LD_32X32B_X32(r, tmem + ch * 32);
            TCGEN05_WAIT_LD();
            #pragma unroll
            for (int j = 0; j < 32; j += 4) {
                float4 o;
                o.x = __uint_as_float(r[j + 0]) + sbias[ch * 32 + j + 0];
                o.y = __uint_as_float(r[j + 1]) + sbias[ch * 32 + j + 1];
                o.z = __uint_as_float(r[j + 2]) + sbias[ch * 32 + j + 2];
                o.w = __uint_as_float(r[j + 3]) + sbias[ch * 32 + j + 3];
                *(float4*)(crow + ch * 32 + j) = o;
            }
        }
    }
    __syncthreads();
    if (wid == 0) TCGEN05_DEALLOC(tmem, 256);
#endif
}

__global__ __launch_bounds__(128, 1) void gemm_qkv_tc(
    const __grid_constant__ CUtensorMap mQa, const __grid_constant__ CUtensorMap mKa,
    const __grid_constant__ CUtensorMap mVa,
    const __grid_constant__ CUtensorMap mQw, const __grid_constant__ CUtensorMap mKw,
    const __grid_constant__ CUtensorMap mVw,
    const float* __restrict__ bq, const float* __restrict__ bk, const float* __restrict__ bv)
{
    int z = blockIdx.z;
    const CUtensorMap* mA = (z == 0) ? &mQa : (z == 1) ? &mKa : &mVa;
    const CUtensorMap* mW = (z == 0) ? &mQw : (z == 1) ? &mKw : &mVw;
    const float* bias     = (z == 0) ? bq   : (z == 1) ? bk   : bv;
    __half* C16           = (z == 0) ? g_Qh : (z == 1) ? g_Kh : nullptr;
    gemm_core(mA, mW, bias, nullptr, C16, (z == 2) ? 2 : 1, (z == 0) ? QSCALE : 1.0f);
}

__global__ __launch_bounds__(128, 1) void gemm_out_tc(
    const __grid_constant__ CUtensorMap mapA,
    const __grid_constant__ CUtensorMap mapW,
    const float* __restrict__ bias, float* __restrict__ C)
{
    gemm_core(&mapA, &mapW, bias, C, nullptr, 0, 1.0f);
}

// ---------------- persistent fp16 flash attention -----------------------------
#define AT_IDESC_S  0x8200010u     // f16 M=128 N=128, fp32 acc
#define AT_IDESC_PV 0x8100010u     // f16 M=128 N=64,  fp32 acc
#define A_SQ   0u
#define A_SK   16384u
#define A_SV   49152u
#define A_SP   65536u
#define A_BB   98304u
#define A_FK(s) (A_BB + 0u + 8u*(s))
#define A_EK(s) (A_BB + 16u + 8u*(s))
#define A_FV    (A_BB + 32u)
#define A_EV    (A_BB + 40u)
#define A_MQ    (A_BB + 48u)
#define A_MS    (A_BB + 56u)
#define A_MPV   (A_BB + 64u)
#define A_SD    (A_BB + 72u)
#define A_PR    (A_BB + 80u)
#define A_QE    (A_BB + 88u)
#define A_TPTR  (A_BB + 96u)
#define A_LSUM  (A_BB + 256u)      // 512B: per-row partial l from half 1
#define A_TOTAL (A_BB + 768u)      // 99072

__global__ __launch_bounds__(320, 2) void attn_tc(
    const __grid_constant__ CUtensorMap mapQ,
    const __grid_constant__ CUtensorMap mapK,
    const __grid_constant__ CUtensorMap mapVt)
{
#if TC_OK
    extern __shared__ __align__(1024) char smem[];
    const uint32_t sb = smem_to_u32(smem);
    const int tid = threadIdx.x, wid = tid >> 5, lane = tid & 31;

    if (tid == 0) {
        #pragma unroll
        for (int s = 0; s < 2; s++) {
            MBARRIER_INIT(sb + A_FK(s), 1);
            MBARRIER_INIT(sb + A_EK(s), 1);
        }
        MBARRIER_INIT(sb + A_FV, 1);
        MBARRIER_INIT(sb + A_EV, 1);
        MBARRIER_INIT(sb + A_MQ, 1);
        MBARRIER_INIT(sb + A_MS, 1);
        MBARRIER_INIT(sb + A_MPV, 1);
        MBARRIER_INIT(sb + A_SD, 8);
        MBARRIER_INIT(sb + A_PR, 8);
        MBARRIER_INIT(sb + A_QE, 1);
        fence_proxy_async();
    }
    if (wid == 0) {
        TCGEN05_ALLOC(sb + A_TPTR, 256);
        TCGEN05_RELINQUISH_ALLOC_PERMIT();
    }
    __syncthreads();
    uint32_t tmem;
    asm volatile("ld.shared.b32 %0, [%1];" : "=r"(tmem) : "r"(sb + A_TPTR));
    const uint32_t tmem_S = tmem, tmem_O = tmem + 128;

    if (tid == 256) {
        // ---- TMA producer (persistent) ----
        int phek[2] = {0, 0}, phev = 0, phqe = 0;
        int kload = 0, vload = 0, qload = 0;
        for (int w = blockIdx.x; w < NWORK; w += NPCTA) {
            const int qt = w & 15, h = (w >> 4) & 15, b = w >> 8;
            if (qload > 0) { MBARRIER_WAIT_PARITY(sb + A_QE, phqe); phqe ^= 1; }
            MBARRIER_EXPECT_TX(sb + A_MQ, 16384);
            tma_load_2d_(sb + A_SQ, &mapQ, h * 64, b * SEQ + qt * 128, sb + A_MQ);
            qload++;
            for (int s = 0; s < 16; s++) {
                const int st = kload & 1;
                if (kload >= 2) { MBARRIER_WAIT_PARITY(sb + A_EK(st), phek[st]); phek[st] ^= 1; }
                MBARRIER_EXPECT_TX(sb + A_FK(st), 16384);
                tma_load_2d_(sb + A_SK + st * 16384, &mapK, h * 64,
                             b * SEQ + s * 128, sb + A_FK(st));
                kload++;
                if (vload >= 1) { MBARRIER_WAIT_PARITY(sb + A_EV, phev); phev ^= 1; }
                MBARRIER_EXPECT_TX(sb + A_FV, 16384);
                #pragma unroll
                for (int c = 0; c < 2; c++)
                    tma_load_2d_(sb + A_SV + c * 8192, &mapVt,
                                 s * 128 + c * 64, (b * NH + h) * HDIM, sb + A_FV);
                vload++;
            }
        }
    } else if (tid == 288) {
        // ---- MMA issuer (persistent) ----
        int phfk[2] = {0, 0}, phfv = 0, phmq = 0, phsd = 0, phpr = 0;
        int kt_total = 0;
        uint64_t adQ = MAKE_SMEM_DESC(sb + A_SQ);
        for (int w = blockIdx.x; w < NWORK; w += NPCTA) {
            MBARRIER_WAIT_PARITY(sb + A_MQ, phmq); phmq ^= 1;
            TCGEN05_FENCE_AFTER();
            for (int kt = 0; kt < 16; kt++) {
                const int st = kt_total & 1;
                if (kt_total > 0) { MBARRIER_WAIT_PARITY(sb + A_SD, phsd); phsd ^= 1; }
                MBARRIER_WAIT_PARITY(sb + A_FK(st), phfk[st]); phfk[st] ^= 1;
                TCGEN05_FENCE_AFTER();
                uint64_t bdK = MAKE_SMEM_DESC(sb + A_SK + st * 16384);
                #pragma unroll
                for (int k = 0; k < 4; k++)
                    mma_f16_ss(tmem_S, adQ + k * 2, bdK + k * 2, AT_IDESC_S, k > 0);
                TCGEN05_COMMIT(sb + A_MS);
                if (kt == 15) TCGEN05_COMMIT(sb + A_QE);  // Q consumable -> reload
                TCGEN05_COMMIT(sb + A_EK(st));
                // PV
                MBARRIER_WAIT_PARITY(sb + A_PR, phpr); phpr ^= 1;
                MBARRIER_WAIT_PARITY(sb + A_FV, phfv); phfv ^= 1;
                TCGEN05_FENCE_AFTER();
                #pragma unroll
                for (int c = 0; c < 8; c++) {
                    uint64_t ad = MAKE_SMEM_DESC(sb + A_SP + (c >> 2) * 16384) + (c & 3) * 2;
                    uint64_t bd = MAKE_SMEM_DESC(sb + A_SV + (c >> 2) * 8192) + (c & 3) * 2;
                    mma_f16_ss(tmem_O, ad, bd, AT_IDESC_PV, (kt > 0) || (c > 0));
                }
                TCGEN05_COMMIT(sb + A_MPV);
                TCGEN05_COMMIT(sb + A_EV);
                kt_total++;
            }
        }
    } else if (wid < 8) {
        // ---- softmax warps (persistent): 32 rows x one 64-col half ----
        const int row  = (wid & 3) * 32 + lane;
        const int half = wid >> 2;
        const uint32_t pbase = A_SP + (uint32_t)half * 16384u;
        int phms = 0, phmpv = 0;
        for (int w = blockIdx.x; w < NWORK; w += NPCTA) {
            const int qt = w & 15, h = (w >> 4) & 15, b = w >> 8;
            const int grow = qt * 128 + row;
            float l = 0.0f;
            const unsigned* mrow = g_maskbits + ((size_t)(b * SEQ + grow)) * MASKW;

            for (int kt = 0; kt < 16; kt++) {
                MBARRIER_WAIT_PARITY(sb + A_MS, phms); phms ^= 1;
                TCGEN05_FENCE_AFTER();
                if (kt > 0) { MBARRIER_WAIT_PARITY(sb + A_MPV, phmpv); phmpv ^= 1; }
                uint32_t r0[32], r1[32];
                TCGEN05_LD_32X32B_X32(r0, tmem_S + half * 64);
                TCGEN05_LD_32X32B_X32(r1, tmem_S + half * 64 + 32);
                TCGEN05_WAIT_LD();
                const unsigned mw0 = mrow[kt * 4 + half * 2];
                const unsigned mw1 = mrow[kt * 4 + half * 2 + 1];
                #pragma unroll
                for (int c2 = 0; c2 < 2; c2++) {
                    const uint32_t* r = c2 ? r1 : r0;
                    const unsigned mw = c2 ? mw1 : mw0;
                    #pragma unroll
                    for (int j = 0; j < 32; j += 8) {
                        float p[8];
                        #pragma unroll
                        for (int t = 0; t < 8; t++) {
                            float e = ex2f(__uint_as_float(r[j + t]));
                            e = ((mw >> (j + t)) & 1u) ? 0.0f : e;
                            l += e;
                            p[t] = e;
                        }
                        uint4 wv_;
                        wv_.x = pack_f16x2(p[0], p[1]);
                        wv_.y = pack_f16x2(p[2], p[3]);
                        wv_.z = pack_f16x2(p[4], p[5]);
                        wv_.w = pack_f16x2(p[6], p[7]);
                        uint32_t off = (uint32_t)row * 128u + (uint32_t)c2 * 64u
                                       + (uint32_t)j * 2u;
                        uint32_t sw  = off ^ ((off >> 3) & 0x70u);
                        *(uint4*)(smem + pbase + sw) = wv_;
                    }
                }
                TCGEN05_FENCE_BEFORE();
                if (lane == 0) MBARRIER_ARRIVE(sb + A_SD);
                fence_proxy_async_shared();
                __syncwarp();
                if (lane == 0) MBARRIER_ARRIVE(sb + A_PR);
            }

            // combine l across halves; epilogue
            if (half == 1) ((float*)(smem + A_LSUM))[row] = l;
            asm volatile("bar.sync 1, 256;" ::: "memory");
            if (half == 0) {
                l += ((float*)(smem + A_LSUM))[row];
                MBARRIER_WAIT_PARITY(sb + A_MPV, phmpv);   // 16th PV of this item
                TCGEN05_FENCE_AFTER();
                uint32_t o0[32], o1[32];
                TCGEN05_LD_32X32B_X32(o0, tmem_O);
                TCGEN05_LD_32X32B_X32(o1, tmem_O + 32);
                TCGEN05_WAIT_LD();
                TCGEN05_FENCE_BEFORE();
                const float inv = 1.0f / l;
                __half* orow = g_AOh + (size_t)(b * SEQ + grow) * DIMN + h * HDIM;
                #pragma unroll
                for (int j = 0; j < 32; j += 8) {
                    uint4 wv_;
                    wv_.x = pack_f16x2(__uint_as_float(o0[j + 0]) * inv, __uint_as_float(o0[j + 1]) * inv);
                    wv_.y = pack_f16x2(__uint_as_float(o0[j + 2]) * inv, __uint_as_float(o0[j + 3]) * inv);
                    wv_.z = pack_f16x2(__uint_as_float(o0[j + 4]) * inv, __uint_as_float(o0[j + 5]) * inv);
                    wv_.w = pack_f16x2(__uint_as_float(o0[j + 6]) * inv, __uint_as_float(o0[j + 7]) * inv);
                    *(uint4*)(orow + j) = wv_;
                }
                #pragma unroll
                for (int j = 0; j < 32; j += 8) {
                    uint4 wv_;
                    wv_.x = pack_f16x2(__uint_as_float(o1[j + 0]) * inv, __uint_as_float(o1[j + 1]) * inv);
                    wv_.y = pack_f16x2(__uint_as_float(o1[j + 2]) * inv, __uint_as_float(o1[j + 3]) * inv);
                    wv_.z = pack_f16x2(__uint_as_float(o1[j + 4]) * inv, __uint_as_float(o1[j + 5]) * inv);
                    wv_.w = pack_f16x2(__uint_as_float(o1[j + 6]) * inv, __uint_as_float(o1[j + 7]) * inv);
                    *(uint4*)(orow + 32 + j) = wv_;
                }
            }
            asm volatile("bar.sync 1, 256;" ::: "memory");
            phmpv ^= 1;   // all softmax warps consume the 16th PV phase together
        }
        if (wid == 0) TCGEN05_DEALLOC(tmem, 256);
    }
#endif  // TC_OK
}

// ---------------- host: tensor maps + launch --------------------------------
typedef CUresult (*EncodeFn)(
    CUtensorMap*, CUtensorMapDataType, cuuint32_t, void*,
    const cuuint64_t*, const cuuint64_t*, const cuuint32_t*, const cuuint32_t*,
    CUtensorMapInterleave, CUtensorMapSwizzle, CUtensorMapL2promotion,
    CUtensorMapFloatOOBfill);

static void make_map(EncodeFn enc, CUtensorMap* m, void* ptr,
                     int cols, int rows, int box0, int box1)
{
    cuuint64_t dims[2]    = {(cuuint64_t)cols, (cuuint64_t)rows};
    cuuint64_t strides[1] = {(cuuint64_t)cols * 2};
    cuuint32_t box[2]     = {(cuuint32_t)box0, (cuuint32_t)box1};
    cuuint32_t es[2]      = {1, 1};
    enc(m, CU_TENSOR_MAP_DATA_TYPE_FLOAT16, 2, ptr, dims, strides, box, es,
        CU_TENSOR_MAP_INTERLEAVE_NONE, CU_TENSOR_MAP_SWIZZLE_128B,
        CU_TENSOR_MAP_L2_PROMOTION_L2_128B, CU_TENSOR_MAP_FLOAT_OOB_FILL_NONE);
}

extern "C" void kernel_launch(void* const* d_in, const int* in_sizes, int n_in,
                              void* d_out, int out_size)
{
    const float* q    = (const float*)d_in[0];
    const float* k    = (const float*)d_in[1];
    const float* v    = (const float*)d_in[2];
    const void*  mask = d_in[3];
    const float* Wq   = (const float*)d_in[4];
    const float* bq   = (const float*)d_in[5];
    const float* Wk   = (const float*)d_in[6];
    const float* bk   = (const float*)d_in[7];
    const float* Wv   = (const float*)d_in[8];
    const float* bv   = (const float*)d_in[9];
    const float* Wo   = (const float*)d_in[10];
    const float* bo   = (const float*)d_in[11];

    void *pQh, *pKh, *pVth, *pAOh, *pqA, *pkA, *pvA, *pwq, *pwk, *pwv, *pwo;
    cudaGetSymbolAddress(&pQh, g_Qh);   cudaGetSymbolAddress(&pKh, g_Kh);
    cudaGetSymbolAddress(&pVth, g_Vth); cudaGetSymbolAddress(&pAOh, g_AOh);
    cudaGetSymbolAddress(&pqA, g_qA);   cudaGetSymbolAddress(&pkA, g_kA);
    cudaGetSymbolAddress(&pvA, g_vA);
    cudaGetSymbolAddress(&pwq, g_wqA);  cudaGetSymbolAddress(&pwk, g_wkA);
    cudaGetSymbolAddress(&pwv, g_wvA);  cudaGetSymbolAddress(&pwo, g_woA);

    EncodeFn enc = nullptr;
    cudaDriverEntryPointQueryResult qres;
    cudaGetDriverEntryPoint("cuTensorMapEncodeTiled", (void**)&enc,
                            cudaEnableDefault, &qres);

    CUtensorMap mQa, mKa, mVa, mAO, mWq, mWk, mWv, mWo;
    make_map(enc, &mQa, pqA, DIMN, MROWS, G_KSTEP, 128);
    make_map(enc, &mKa, pkA, DIMN, MROWS, G_KSTEP, 128);
    make_map(enc, &mVa, pvA, DIMN, MROWS, G_KSTEP, 128);
    make_map(enc, &mAO, pAOh, DIMN, MROWS, G_KSTEP, 128);
    make_map(enc, &mWq, pwq, DIMN, DIMN, G_KSTEP, 256);
    make_map(enc, &mWk, pwk, DIMN, DIMN, G_KSTEP, 256);
    make_map(enc, &mWv, pwv, DIMN, DIMN, G_KSTEP, 256);
    make_map(enc, &mWo, pwo, DIMN, DIMN, G_KSTEP, 256);
    CUtensorMap mAQ, mAK, mAVt;
    make_map(enc, &mAQ,  pQh,  DIMN, MROWS, 64, 128);
    make_map(enc, &mAK,  pKh,  DIMN, MROWS, 64, 128);
    make_map(enc, &mAVt, pVth, SEQ,  BATCH * DIMN, 64, 64);

    cudaFuncSetAttribute(gemm_qkv_tc, cudaFuncAttributeMaxDynamicSharedMemorySize, G_SMEM_TOTAL);
    cudaFuncSetAttribute(gemm_out_tc, cudaFuncAttributeMaxDynamicSharedMemorySize, G_SMEM_TOTAL);
    cudaFuncSetAttribute(attn_tc,     cudaFuncAttributeMaxDynamicSharedMemorySize, A_TOTAL);

    // prep: fp16 rounding of 7 tensors + mask sniff, one launch
    prep_all<<<dim3(4096, 8), 256>>>(q, k, v, Wq, Wk, Wv, Wo, (const unsigned*)mask);

    // mask bit-pack
    {
        int nw = BATCH * SEQ * MASKW;
        pack_mask<<<(nw + 255) / 256, 256>>>(mask);
    }

    // QKV projections
    gemm_qkv_tc<<<dim3(DIMN / 256, MROWS / 128, 3), 128, G_SMEM_TOTAL>>>(
        mQa, mKa, mVa, mWq, mWk, mWv, bq, bk, bv);

    // persistent fp16 flash attention
    attn_tc<<<NPCTA, 320, A_TOTAL>>>(mAQ, mAK, mAVt);

    // output projection
    gemm_out_tc<<<dim3(DIMN / 256, MROWS / 128), 128, G_SMEM_TOTAL>>>(
        mAO, mWo, bo, (float*)d_out);
}

// round 17
// speedup vs baseline: 1.0449x; 1.0449x over previous
#include <cuda_runtime.h>
#include <cuda.h>
#include <cuda_fp16.h>
#include <cstdint>

#if !defined(__CUDA_ARCH__) || defined(__CUDA_ARCH_FEAT_SM103_ALL)
#define TC_OK 1
#else
#define TC_OK 0
#endif

// ---------------- problem constants ----------------------------------------
#define DIMN   1024
#define SEQ    2048
#define BATCH  2
#define NH     16
#define HDIM   64
#define MROWS  (BATCH*SEQ)              // 4096
#define MASKW  (SEQ/32)                 // 64 words per (b,q) row
#define QSCALE 0.045084220f             // (1/32)*log2(e): p = ex2(S)

// ---------------- scratch (static device globals) ---------------------------
__device__ __align__(1024) __half g_Qh [(size_t)MROWS*DIMN];
__device__ __align__(1024) __half g_Kh [(size_t)MROWS*DIMN];
__device__ __align__(1024) __half g_Vth[(size_t)BATCH*DIMN*SEQ]; // [b*1024+d][s]
__device__ __align__(1024) __half g_AOh[(size_t)MROWS*DIMN];
__device__ __align__(1024) __half g_qA[(size_t)MROWS*DIMN];
__device__ __align__(1024) __half g_kA[(size_t)MROWS*DIMN];
__device__ __align__(1024) __half g_vA[(size_t)MROWS*DIMN];
__device__ __align__(1024) __half g_wqA[(size_t)DIMN*DIMN];
__device__ __align__(1024) __half g_wkA[(size_t)DIMN*DIMN];
__device__ __align__(1024) __half g_wvA[(size_t)DIMN*DIMN];
__device__ __align__(1024) __half g_woA[(size_t)DIMN*DIMN];
__device__ unsigned g_maskbits[(size_t)BATCH*SEQ*MASKW];  // 1 = masked
__device__ unsigned g_flags = 0;

// ---------------- PTX helpers ----------------------------------------------
__device__ __forceinline__ uint32_t smem_to_u32(const void* smem_ptr) {
    uint32_t addr;
    asm("{ .reg .u64 tmp; cvta.to.shared.u64 tmp, %1; cvt.u32.u64 %0, tmp; }"
        : "=r"(addr) : "l"(smem_ptr));
    return addr;
}
__device__ __forceinline__ void fence_proxy_async() {
    asm volatile("fence.proxy.async;" ::: "memory");
}
__device__ __forceinline__ void fence_proxy_async_shared() {
    asm volatile("fence.proxy.async.shared::cta;" ::: "memory");
}
__device__ __forceinline__ uint32_t pack_f16x2(float lo, float hi) {
    uint32_t d;
    asm("cvt.rn.f16x2.f32 %0, %1, %2;" : "=r"(d) : "f"(hi), "f"(lo));
    return d;
}
__device__ __forceinline__ float ex2f(float x) {
    float r;
    asm("ex2.approx.f32 %0, %1;" : "=f"(r) : "f"(x));
    return r;
}

#define MBARRIER_INIT(mbar, count) \
    asm volatile("mbarrier.init.shared.b64 [%0], %1;" \
        :: "r"((uint32_t)(mbar)), "r"((uint32_t)(count)) : "memory")

#define MBARRIER_ARRIVE(mbar) \
    asm volatile("mbarrier.arrive.shared.b64 _, [%0];" \
        :: "r"((uint32_t)(mbar)) : "memory")

#define MBARRIER_EXPECT_TX(mbar, tx_bytes) \
    asm volatile("mbarrier.arrive.expect_tx.shared.b64 _, [%0], %1;" \
        :: "r"((uint32_t)(mbar)), "r"((uint32_t)(tx_bytes)) : "memory")

#define MBARRIER_WAIT_PARITY(mbar_smem_addr, phase_parity) do { \
    uint32_t _mbar = (uint32_t)(mbar_smem_addr); \
    uint32_t _parity = (uint32_t)(phase_parity); \
    uint32_t _done; \
    asm volatile( \
        "{\n\t.reg .pred p;\n\t" \
        "mbarrier.try_wait.parity.acquire.cta.shared::cta.b64 p, [%1], %2;\n\t" \
        "selp.b32 %0, 1, 0, p;\n\t}" \
        : "=r"(_done) : "r"(_mbar), "r"(_parity) : "memory"); \
    if (!_done) { \
        asm volatile( \
            "{\n\t.reg .pred P1;\n\t" \
            "WAIT_LOOP_%=:\n\t" \
            "mbarrier.try_wait.parity.acquire.cta.shared::cta.b64 P1, [%0], %1, 0x989680;\n\t" \
            "@P1 bra.uni WAIT_DONE_%=;\n\t" \
            "bra.uni WAIT_LOOP_%=;\n\t" \
            "WAIT_DONE_%=:\n\t}" \
            :: "r"(_mbar), "r"(_parity) : "memory"); \
    } \
} while(0)

#define TCGEN05_ALLOC(smem_result_addr, nCols) \
    asm volatile("tcgen05.alloc.cta_group::1.sync.aligned.shared::cta.b32 [%0], %1;" \
        :: "r"((uint32_t)(smem_result_addr)), "r"((uint32_t)(nCols)) : "memory")
#define TCGEN05_DEALLOC(tmem_addr, nCols) \
    asm volatile("tcgen05.dealloc.cta_group::1.sync.aligned.b32 %0, %1;" \
        :: "r"(tmem_addr), "r"(nCols))
#define TCGEN05_RELINQUISH_ALLOC_PERMIT() \
    asm volatile("tcgen05.relinquish_alloc_permit.cta_group::1.sync.aligned;")
#define TCGEN05_COMMIT(mbar) \
    asm volatile("tcgen05.commit.cta_group::1.mbarrier::arrive::one.shared::cluster.b64 [%0];" \
        :: "r"((uint32_t)(mbar)) : "memory")
#define TCGEN05_WAIT_LD() \
    asm volatile("tcgen05.wait::ld.sync.aligned;" ::: "memory")
#define TCGEN05_FENCE_BEFORE() \
    asm volatile("tcgen05.fence::before_thread_sync;" ::: "memory")
#define TCGEN05_FENCE_AFTER() \
    asm volatile("tcgen05.fence::after_thread_sync;" ::: "memory")

#define TCGEN05_LD_32X32B_X32(r, tmem_addr) \
    asm volatile( \
        "tcgen05.ld.sync.aligned.32x32b.x32.b32 " \
        "{%0, %1, %2, %3, %4, %5, %6, %7, " \
        " %8, %9, %10, %11, %12, %13, %14, %15, " \
        " %16, %17, %18, %19, %20, %21, %22, %23, " \
        " %24, %25, %26, %27, %28, %29, %30, %31}, [%32];" \
        : "=r"((r)[0]),  "=r"((r)[1]),  "=r"((r)[2]),  "=r"((r)[3]), \
          "=r"((r)[4]),  "=r"((r)[5]),  "=r"((r)[6]),  "=r"((r)[7]), \
          "=r"((r)[8]),  "=r"((r)[9]),  "=r"((r)[10]), "=r"((r)[11]), \
          "=r"((r)[12]), "=r"((r)[13]), "=r"((r)[14]), "=r"((r)[15]), \
          "=r"((r)[16]), "=r"((r)[17]), "=r"((r)[18]), "=r"((r)[19]), \
          "=r"((r)[20]), "=r"((r)[21]), "=r"((r)[22]), "=r"((r)[23]), \
          "=r"((r)[24]), "=r"((r)[25]), "=r"((r)[26]), "=r"((r)[27]), \
          "=r"((r)[28]), "=r"((r)[29]), "=r"((r)[30]), "=r"((r)[31]) \
        : "r"(tmem_addr))

static constexpr uint64_t SMEM_DESC_BASE_SW128 =
    (uint64_t(2)  << 61) | (uint64_t(1) << 46) | (uint64_t(64) << 32) | (uint64_t(1) << 16);
#define MAKE_SMEM_DESC(base_addr) \
    (SMEM_DESC_BASE_SW128 | ((uint64_t)((base_addr) >> 4) & 0x3FFF))

__device__ __forceinline__ void tma_load_2d_(
    uint32_t smem_addr, const void* tensor_map,
    int32_t cx, int32_t cy, uint32_t mbar)
{
    asm volatile(
        "cp.async.bulk.tensor.2d.shared::cta.global.tile.mbarrier::complete_tx::bytes "
        "[%0], [%1, {%2, %3}], [%4];"
        :: "r"(smem_addr), "l"(tensor_map), "r"(cx), "r"(cy), "r"(mbar)
        : "memory");
}

__device__ __forceinline__ void mma_f16_ss(
    uint32_t d_tmem, uint64_t a_desc, uint64_t b_desc, uint32_t idesc, bool acc)
{
#if TC_OK
    uint32_t e = acc ? 1u : 0u;
    asm volatile(
        "{\n\t.reg .pred p;\n\t"
        "setp.ne.u32 p, %4, 0;\n\t"
        "tcgen05.mma.cta_group::1.kind::f16 [%0], %1, %2, %3, p;\n\t}"
        :: "r"(d_tmem), "l"(a_desc), "l"(b_desc), "r"(idesc), "r"(e)
        : "memory");
#endif
}

// ---------------- prep: fp16 rounding (z 0-6) + mask sniff (z 7) ------------
__global__ __launch_bounds__(256) void prep_all(
    const float* __restrict__ q, const float* __restrict__ k, const float* __restrict__ v,
    const float* __restrict__ wq, const float* __restrict__ wk,
    const float* __restrict__ wv, const float* __restrict__ wo,
    const unsigned* __restrict__ mask)
{
    const int z = blockIdx.y;
    if (z == 7) {
        unsigned vv = mask[blockIdx.x * 256 + threadIdx.x];
        unsigned f = 0;
        if (vv != 0u && vv != 1u) {
            if (vv == 0x3F800000u)                     f = 2u;
            else if (vv == 0x3F80u || vv == 0x3F803F80u) f = 4u;
            else                                        f = 1u;
        }
        f = __reduce_or_sync(0xFFFFFFFFu, f);
        if ((threadIdx.x & 31) == 0 && f) atomicOr(&g_flags, f);
        return;
    }
    const float* in; __half* out;
    switch (z) {
        case 0: in = q;  out = g_qA;  break;
        case 1: in = k;  out = g_kA;  break;
        case 2: in = v;  out = g_vA;  break;
        case 3: in = wq; out = g_wqA; break;
        case 4: in = wk; out = g_wkA; break;
        case 5: in = wv; out = g_wvA; break;
        default: in = wo; out = g_woA; break;
    }
    if (z >= 3 && blockIdx.x >= 1024) return;
    int i = (blockIdx.x * 256 + threadIdx.x) * 4;
    float4 t = *(const float4*)(in + i);
    uint2 w;
    w.x = pack_f16x2(t.x, t.y);
    w.y = pack_f16x2(t.z, t.w);
    *(uint2*)(out + i) = w;
}

__global__ void pack_mask(const void* __restrict__ mask)
{
    int w = blockIdx.x * blockDim.x + threadIdx.x;
    const int NW = BATCH * SEQ * MASKW;
    if (w >= NW) return;
    unsigned ff = g_flags;
    int mode = (ff & 4u) ? 3 : (ff & 2u) ? 1 : (ff & 1u) ? 2 : 0;
    size_t base = (size_t)w * 32;
    unsigned bits = 0;
    if (mode == 0) {
        const int* p = (const int*)mask;
        #pragma unroll
        for (int j = 0; j < 32; j++) if (p[base + j] != 0) bits |= 1u << j;
    } else if (mode == 1) {
        const float* p = (const float*)mask;
        #pragma unroll
        for (int j = 0; j < 32; j++) if (p[base + j] != 0.0f) bits |= 1u << j;
    } else if (mode == 2) {
        const unsigned char* p = (const unsigned char*)mask;
        #pragma unroll
        for (int j = 0; j < 32; j++) if (p[base + j] != 0) bits |= 1u << j;
    } else {
        const unsigned short* p = (const unsigned short*)mask;
        #pragma unroll
        for (int j = 0; j < 32; j++) if (p[base + j] != 0) bits |= 1u << j;
    }
    g_maskbits[w] = bits;
}

// ---------------- tcgen05 fp16 GEMM core ------------------------------------
#define G_NSTAGE 3
#define G_KSTEP  64
#define G_KITERS (DIMN / G_KSTEP)           // 16
#define G_STAGE_A_BYTES (128 * 128)
#define G_STAGE_B_BYTES (256 * 128)
#define G_STAGE_BYTES   (G_STAGE_A_BYTES + G_STAGE_B_BYTES)
#define G_SMEM_STAGE0   2048
#define G_SMEM_TOTAL    (G_SMEM_STAGE0 + G_NSTAGE * G_STAGE_BYTES)   // 149504
#define G_IDESC 0x8400010u      // f16, M=128, N=256, fp32 acc

__device__ __forceinline__ void gemm_core(
    const CUtensorMap* mapA, const CUtensorMap* mapW,
    const float* __restrict__ bias, float* __restrict__ C,
    __half* __restrict__ C16, int mode, float oscale)
{
#if TC_OK
    extern __shared__ __align__(1024) char smem[];
    const uint32_t sb = smem_to_u32(smem);
    const uint32_t fullb  = sb;
    const uint32_t emptyb = sb + 8;
    const uint32_t doneb  = sb + 48;
    const uint32_t tptr   = sb + 64;
    float* sbias = (float*)(smem + 1024);

    const int tid = threadIdx.x, wid = tid >> 5, lid = tid & 31;
    const int bx = blockIdx.x, by = blockIdx.y;

    if (tid == 0) {
        #pragma unroll
        for (int s = 0; s < G_NSTAGE; s++) {
            MBARRIER_INIT(fullb  + 16 * s, 1);
            MBARRIER_INIT(emptyb + 16 * s, 1);
        }
        MBARRIER_INIT(doneb, 1);
        fence_proxy_async();
    }
    if (wid == 0) {
        TCGEN05_ALLOC(tptr, 256);
        TCGEN05_RELINQUISH_ALLOC_PERMIT();
    }
    sbias[tid]       = bias[bx * 256 + tid];
    sbias[tid + 128] = bias[bx * 256 + tid + 128];
    __syncthreads();

    uint32_t tmem;
    asm volatile("ld.shared.b32 %0, [%1];" : "=r"(tmem) : "r"(tptr));

    if (tid == 0) {
        int st = 0, ph = 1;
        for (int s = 0; s < G_KITERS; s++) {
            MBARRIER_WAIT_PARITY(emptyb + 16 * st, ph);
            MBARRIER_EXPECT_TX(fullb + 16 * st, G_STAGE_BYTES);
            uint32_t sa = sb + G_SMEM_STAGE0 + st * G_STAGE_BYTES;
            tma_load_2d_(sa,                   mapA, s * G_KSTEP, by * 128, fullb + 16 * st);
            tma_load_2d_(sa + G_STAGE_A_BYTES, mapW, s * G_KSTEP, bx * 256, fullb + 16 * st);
            if (++st == G_NSTAGE) { st = 0; ph ^= 1; }
        }
    } else if (tid == 32) {
        int st = 0, ph = 0;
        for (int s = 0; s < G_KITERS; s++) {
            MBARRIER_WAIT_PARITY(fullb + 16 * st, ph);
            uint32_t sa = sb + G_SMEM_STAGE0 + st * G_STAGE_BYTES;
            uint64_t ad = MAKE_SMEM_DESC(sa);
            uint64_t bd = MAKE_SMEM_DESC(sa + G_STAGE_A_BYTES);
            #pragma unroll
            for (int k = 0; k < 4; k++)
                mma_f16_ss(tmem, ad + k * 2, bd + k * 2, G_IDESC, (s > 0) || (k > 0));
            TCGEN05_COMMIT(emptyb + 16 * st);
            if (++st == G_NSTAGE) { st = 0; ph ^= 1; }
        }
        TCGEN05_COMMIT(doneb);
    }

    MBARRIER_WAIT_PARITY(doneb, 0);
    TCGEN05_FENCE_AFTER();

    const int m = by * 128 + wid * 32 + lid;
    if (mode == 2) {
        const int bb = m >> 11, s = m & (SEQ - 1);
        __half* base = g_Vth + (size_t)bb * DIMN * SEQ + s;
        #pragma unroll
        for (int ch = 0; ch < 8; ch++) {
            uint32_t r[32];
            TCGEN05_LD_32X32B_X32(r, tmem + ch * 32);
            TCGEN05_WAIT_LD();
            #pragma unroll
            for (int j = 0; j < 32; j++) {
                int n = bx * 256 + ch * 32 + j;
                base[(size_t)n * SEQ] =
                    __float2half_rn(__uint_as_float(r[j]) + sbias[ch * 32 + j]);
            }
        }
    } else if (mode == 1) {
        __half* crow = C16 + (size_t)m * DIMN + bx * 256;
        #pragma unroll
        for (int ch = 0; ch < 8; ch++) {
            uint32_t r[32];
            TCGEN05_LD_32X32B_X32(r, tmem + ch * 32);
            TCGEN05_WAIT_LD();
            #pragma unroll
            for (int j = 0; j < 32; j += 8) {
                float v[8];
                #pragma unroll
                for (int t = 0; t < 8; t++)
                    v[t] = (__uint_as_float(r[j + t]) + sbias[ch * 32 + j + t]) * oscale;
                uint4 w;
                w.x = pack_f16x2(v[0], v[1]);
                w.y = pack_f16x2(v[2], v[3]);
                w.z = pack_f16x2(v[4], v[5]);
                w.w = pack_f16x2(v[6], v[7]);
                *(uint4*)(crow + ch * 32 + j) = w;
            }
        }
    } else {
        float* crow = C + (size_t)m * DIMN + bx * 256;
        #pragma unroll
        for (int ch = 0; ch < 8; ch++) {
            uint32_t r[32];
            TCGEN05_LD_32X32B_X32(r, tmem + ch * 32);
            TCGEN05_WAIT_LD();
            #pragma unroll
            for (int j = 0; j < 32; j += 4) {
                float4 o;
                o.x = __uint_as_float(r[j + 0]) + sbias[ch * 32 + j + 0];
                o.y = __uint_as_float(r[j + 1]) + sbias[ch * 32 + j + 1];
                o.z = __uint_as_float(r[j + 2]) + sbias[ch * 32 + j + 2];
                o.w = __uint_as_float(r[j + 3]) + sbias[ch * 32 + j + 3];
                *(float4*)(crow + ch * 32 + j) = o;
            }
        }
    }
    __syncthreads();
    if (wid == 0) TCGEN05_DEALLOC(tmem, 256);
#endif
}

__global__ __launch_bounds__(128, 1) void gemm_qkv_tc(
    const __grid_constant__ CUtensorMap mQa, const __grid_constant__ CUtensorMap mKa,
    const __grid_constant__ CUtensorMap mVa,
    const __grid_constant__ CUtensorMap mQw, const __grid_constant__ CUtensorMap mKw,
    const __grid_constant__ CUtensorMap mVw,
    const float* __restrict__ bq, const float* __restrict__ bk, const float* __restrict__ bv)
{
    int z = blockIdx.z;
    const CUtensorMap* mA = (z == 0) ? &mQa : (z == 1) ? &mKa : &mVa;
    const CUtensorMap* mW = (z == 0) ? &mQw : (z == 1) ? &mKw : &mVw;
    const float* bias     = (z == 0) ? bq   : (z == 1) ? bk   : bv;
    __half* C16           = (z == 0) ? g_Qh : (z == 1) ? g_Kh : nullptr;
    gemm_core(mA, mW, bias, nullptr, C16, (z == 2) ? 2 : 1, (z == 0) ? QSCALE : 1.0f);
}

__global__ __launch_bounds__(128, 1) void gemm_out_tc(
    const __grid_constant__ CUtensorMap mapA,
    const __grid_constant__ CUtensorMap mapW,
    const float* __restrict__ bias, float* __restrict__ C)
{
    gemm_core(&mapA, &mapW, bias, C, nullptr, 0, 1.0f);
}

// ---------------- fp16 flash attention: 64-key tiles, S+P double-buffered ----
// 320 threads: warps 0-7 softmax (warp w: rows (w&3)*32+lane, 32-col half w>>2
// of the 64-key tile), tid 256 TMA, tid 288 MMA issuer. 2 CTAs/SM.
// TMEM alloc 256: S0 @0 (64), S1 @64, O @128 (64).
#define AT_IDESC 0x8100010u     // f16 M=128 N=64, fp32 acc (S and PV)
#define NKT    32               // 64-key tiles
#define A_SQ   0u
#define A_SK   16384u            // 2 x 8KB
#define A_SV   32768u            // 2 x 8KB
#define A_SP   49152u            // 2 x 16KB
#define A_BB   81920u
#define A_FK(s)  (A_BB + 0u + 8u*(s))
#define A_EK(s)  (A_BB + 16u + 8u*(s))
#define A_FV(s)  (A_BB + 32u + 8u*(s))
#define A_EV(s)  (A_BB + 48u + 8u*(s))
#define A_MS(s)  (A_BB + 64u + 8u*(s))
#define A_MPV(s) (A_BB + 80u + 8u*(s))
#define A_SD(s)  (A_BB + 96u + 8u*(s))
#define A_PR(s)  (A_BB + 112u + 8u*(s))
#define A_MQ     (A_BB + 128u)
#define A_TPTR   (A_BB + 136u)
#define A_LSUM   (A_BB + 256u)   // 512B
#define A_TOTAL  (A_BB + 768u)   // 82688

__global__ __launch_bounds__(320, 2) void attn_tc(
    const __grid_constant__ CUtensorMap mapQ,
    const __grid_constant__ CUtensorMap mapK,
    const __grid_constant__ CUtensorMap mapVt)
{
#if TC_OK
    extern __shared__ __align__(1024) char smem[];
    const uint32_t sb = smem_to_u32(smem);
    const int tid = threadIdx.x, wid = tid >> 5, lane = tid & 31;
    const int qt = blockIdx.x, h = blockIdx.y, b = blockIdx.z;

    if (tid == 0) {
        #pragma unroll
        for (int s = 0; s < 2; s++) {
            MBARRIER_INIT(sb + A_FK(s), 1);
            MBARRIER_INIT(sb + A_EK(s), 1);
            MBARRIER_INIT(sb + A_FV(s), 1);
            MBARRIER_INIT(sb + A_EV(s), 1);
            MBARRIER_INIT(sb + A_MS(s), 1);
            MBARRIER_INIT(sb + A_MPV(s), 1);
            MBARRIER_INIT(sb + A_SD(s), 8);
            MBARRIER_INIT(sb + A_PR(s), 8);
        }
        MBARRIER_INIT(sb + A_MQ, 1);
        fence_proxy_async();
    }
    if (wid == 0) {
        TCGEN05_ALLOC(sb + A_TPTR, 256);
        TCGEN05_RELINQUISH_ALLOC_PERMIT();
    }
    __syncthreads();
    uint32_t tmem;
    asm volatile("ld.shared.b32 %0, [%1];" : "=r"(tmem) : "r"(sb + A_TPTR));
    const uint32_t tmem_O = tmem + 128;

    if (tid == 256) {
        // ---- TMA producer ----
        MBARRIER_EXPECT_TX(sb + A_MQ, 16384);
        tma_load_2d_(sb + A_SQ, &mapQ, h * 64, b * SEQ + qt * 128, sb + A_MQ);
        int phek[2] = {0, 0}, phev[2] = {0, 0};
        for (int s = 0; s < NKT; s++) {
            const int st = s & 1;
            if (s >= 2) { MBARRIER_WAIT_PARITY(sb + A_EK(st), phek[st]); phek[st] ^= 1; }
            MBARRIER_EXPECT_TX(sb + A_FK(st), 8192);
            tma_load_2d_(sb + A_SK + st * 8192, &mapK, h * 64, b * SEQ + s * 64, sb + A_FK(st));
            if (s >= 2) { MBARRIER_WAIT_PARITY(sb + A_EV(st), phev[st]); phev[st] ^= 1; }
            MBARRIER_EXPECT_TX(sb + A_FV(st), 8192);
            tma_load_2d_(sb + A_SV + st * 8192, &mapVt, s * 64, (b * NH + h) * HDIM, sb + A_FV(st));
        }
    } else if (tid == 288) {
        // ---- MMA issuer ----
        int phfk[2] = {0, 0}, phfv[2] = {0, 0}, phsd[2] = {0, 0}, phpr[2] = {0, 0};
        MBARRIER_WAIT_PARITY(sb + A_MQ, 0);
        TCGEN05_FENCE_AFTER();
        uint64_t adQ = MAKE_SMEM_DESC(sb + A_SQ);
        // S(0)
        MBARRIER_WAIT_PARITY(sb + A_FK(0), 0); phfk[0] ^= 1;
        {
            uint64_t bdK = MAKE_SMEM_DESC(sb + A_SK);
            #pragma unroll
            for (int k = 0; k < 4; k++)
                mma_f16_ss(tmem, adQ + k * 2, bdK + k * 2, AT_IDESC, k > 0);
        }
        TCGEN05_COMMIT(sb + A_MS(0));
        TCGEN05_COMMIT(sb + A_EK(0));

        for (int kt = 0; kt < NKT; kt++) {
            // S(kt+1) into the other buffer (overlaps softmax of kt)
            if (kt + 1 < NKT) {
                const int s2 = (kt + 1) & 1;
                if (kt + 1 >= 2) { MBARRIER_WAIT_PARITY(sb + A_SD(s2), phsd[s2]); phsd[s2] ^= 1; }
                MBARRIER_WAIT_PARITY(sb + A_FK(s2), phfk[s2]); phfk[s2] ^= 1;
                TCGEN05_FENCE_AFTER();
                uint64_t bdK = MAKE_SMEM_DESC(sb + A_SK + s2 * 8192);
                #pragma unroll
                for (int k = 0; k < 4; k++)
                    mma_f16_ss(tmem + s2 * 64, adQ + k * 2, bdK + k * 2, AT_IDESC, k > 0);
                TCGEN05_COMMIT(sb + A_MS(s2));
                TCGEN05_COMMIT(sb + A_EK(s2));
            }
            // PV(kt)
            const int p2 = kt & 1;
            MBARRIER_WAIT_PARITY(sb + A_PR(p2), phpr[p2]); phpr[p2] ^= 1;
            MBARRIER_WAIT_PARITY(sb + A_FV(p2), phfv[p2]); phfv[p2] ^= 1;
            TCGEN05_FENCE_AFTER();
            uint64_t adP = MAKE_SMEM_DESC(sb + A_SP + p2 * 16384);
            uint64_t bdV = MAKE_SMEM_DESC(sb + A_SV + p2 * 8192);
            #pragma unroll
            for (int k = 0; k < 4; k++)
                mma_f16_ss(tmem_O, adP + k * 2, bdV + k * 2, AT_IDESC, (kt > 0) || (k > 0));
            TCGEN05_COMMIT(sb + A_MPV(p2));
            TCGEN05_COMMIT(sb + A_EV(p2));
        }
    } else if (wid < 8) {
        // ---- softmax warps: 32 rows x 32-col half of the 64-key tile ----
        const int row  = (wid & 3) * 32 + lane;
        const int half = wid >> 2;
        const int grow = qt * 128 + row;
        float l = 0.0f;
        const unsigned* mrow = g_maskbits + ((size_t)(b * SEQ + grow)) * MASKW;
        int phms[2] = {0, 0}, phmpv[2] = {0, 0};

        for (int kt = 0; kt < NKT; kt++) {
            const int s2 = kt & 1;
            MBARRIER_WAIT_PARITY(sb + A_MS(s2), phms[s2]); phms[s2] ^= 1;
            TCGEN05_FENCE_AFTER();
            uint32_t r[32];
            TCGEN05_LD_32X32B_X32(r, tmem + s2 * 64 + half * 32);
            TCGEN05_WAIT_LD();
            // S buffer consumed -> release for S-MMA(kt+2)
            TCGEN05_FENCE_BEFORE();
            if (lane == 0) MBARRIER_ARRIVE(sb + A_SD(s2));
            // P[s2] free once PV(kt-2) done
            if (kt >= 2) { MBARRIER_WAIT_PARITY(sb + A_MPV(s2), phmpv[s2]); phmpv[s2] ^= 1; }
            const unsigned mw = mrow[kt * 2 + half];
            #pragma unroll
            for (int j = 0; j < 32; j += 8) {
                float p[8];
                #pragma unroll
                for (int t = 0; t < 8; t++) {
                    float e = ex2f(__uint_as_float(r[j + t]));
                    e = ((mw >> (j + t)) & 1u) ? 0.0f : e;
                    l += e;
                    p[t] = e;
                }
                uint4 wv_;
                wv_.x = pack_f16x2(p[0], p[1]);
                wv_.y = pack_f16x2(p[2], p[3]);
                wv_.z = pack_f16x2(p[4], p[5]);
                wv_.w = pack_f16x2(p[6], p[7]);
                uint32_t off = (uint32_t)row * 128u + (uint32_t)half * 64u + (uint32_t)j * 2u;
                uint32_t sw  = off ^ ((off >> 3) & 0x70u);
                *(uint4*)(smem + A_SP + (uint32_t)s2 * 16384u + sw) = wv_;
            }
            fence_proxy_async_shared();
            __syncwarp();
            if (lane == 0) MBARRIER_ARRIVE(sb + A_PR(s2));
        }

        // combine l across halves; epilogue
        if (half == 1) ((float*)(smem + A_LSUM))[row] = l;
        asm volatile("bar.sync 1, 256;" ::: "memory");
        if (half == 0) {
            l += ((float*)(smem + A_LSUM))[row];
            MBARRIER_WAIT_PARITY(sb + A_MPV(1), phmpv[1]);   // PV(31), 16th on buf 1
            TCGEN05_FENCE_AFTER();
            uint32_t o0[32], o1[32];
            TCGEN05_LD_32X32B_X32(o0, tmem_O);
            TCGEN05_LD_32X32B_X32(o1, tmem_O + 32);
            TCGEN05_WAIT_LD();
            TCGEN05_FENCE_BEFORE();
            const float inv = 1.0f / l;
            __half* orow = g_AOh + (size_t)(b * SEQ + grow) * DIMN + h * HDIM;
            #pragma unroll
            for (int j = 0; j < 32; j += 8) {
                uint4 wv_;
                wv_.x = pack_f16x2(__uint_as_float(o0[j + 0]) * inv, __uint_as_float(o0[j + 1]) * inv);
                wv_.y = pack_f16x2(__uint_as_float(o0[j + 2]) * inv, __uint_as_float(o0[j + 3]) * inv);
                wv_.z = pack_f16x2(__uint_as_float(o0[j + 4]) * inv, __uint_as_float(o0[j + 5]) * inv);
                wv_.w = pack_f16x2(__uint_as_float(o0[j + 6]) * inv, __uint_as_float(o0[j + 7]) * inv);
                *(uint4*)(orow + j) = wv_;
            }
            #pragma unroll
            for (int j = 0; j < 32; j += 8) {
                uint4 wv_;
                wv_.x = pack_f16x2(__uint_as_float(o1[j + 0]) * inv, __uint_as_float(o1[j + 1]) * inv);
                wv_.y = pack_f16x2(__uint_as_float(o1[j + 2]) * inv, __uint_as_float(o1[j + 3]) * inv);
                wv_.z = pack_f16x2(__uint_as_float(o1[j + 4]) * inv, __uint_as_float(o1[j + 5]) * inv);
                wv_.w = pack_f16x2(__uint_as_float(o1[j + 6]) * inv, __uint_as_float(o1[j + 7]) * inv);
                *(uint4*)(orow + 32 + j) = wv_;
            }
        }
        asm volatile("bar.sync 1, 256;" ::: "memory");
        if (wid == 0) TCGEN05_DEALLOC(tmem, 256);
    }
#endif  // TC_OK
}

// ---------------- host: tensor maps + launch --------------------------------
typedef CUresult (*EncodeFn)(
    CUtensorMap*, CUtensorMapDataType, cuuint32_t, void*,
    const cuuint64_t*, const cuuint64_t*, const cuuint32_t*, const cuuint32_t*,
    CUtensorMapInterleave, CUtensorMapSwizzle, CUtensorMapL2promotion,
    CUtensorMapFloatOOBfill);

static void make_map(EncodeFn enc, CUtensorMap* m, void* ptr,
                     int cols, int rows, int box0, int box1)
{
    cuuint64_t dims[2]    = {(cuuint64_t)cols, (cuuint64_t)rows};
    cuuint64_t strides[1] = {(cuuint64_t)cols * 2};
    cuuint32_t box[2]     = {(cuuint32_t)box0, (cuuint32_t)box1};
    cuuint32_t es[2]      = {1, 1};
    enc(m, CU_TENSOR_MAP_DATA_TYPE_FLOAT16, 2, ptr, dims, strides, box, es,
        CU_TENSOR_MAP_INTERLEAVE_NONE, CU_TENSOR_MAP_SWIZZLE_128B,
        CU_TENSOR_MAP_L2_PROMOTION_L2_128B, CU_TENSOR_MAP_FLOAT_OOB_FILL_NONE);
}

extern "C" void kernel_launch(void* const* d_in, const int* in_sizes, int n_in,
                              void* d_out, int out_size)
{
    const float* q    = (const float*)d_in[0];
    const float* k    = (const float*)d_in[1];
    const float* v    = (const float*)d_in[2];
    const void*  mask = d_in[3];
    const float* Wq   = (const float*)d_in[4];
    const float* bq   = (const float*)d_in[5];
    const float* Wk   = (const float*)d_in[6];
    const float* bk   = (const float*)d_in[7];
    const float* Wv   = (const float*)d_in[8];
    const float* bv   = (const float*)d_in[9];
    const float* Wo   = (const float*)d_in[10];
    const float* bo   = (const float*)d_in[11];

    void *pQh, *pKh, *pVth, *pAOh, *pqA, *pkA, *pvA, *pwq, *pwk, *pwv, *pwo;
    cudaGetSymbolAddress(&pQh, g_Qh);   cudaGetSymbolAddress(&pKh, g_Kh);
    cudaGetSymbolAddress(&pVth, g_Vth); cudaGetSymbolAddress(&pAOh, g_AOh);
    cudaGetSymbolAddress(&pqA, g_qA);   cudaGetSymbolAddress(&pkA, g_kA);
    cudaGetSymbolAddress(&pvA, g_vA);
    cudaGetSymbolAddress(&pwq, g_wqA);  cudaGetSymbolAddress(&pwk, g_wkA);
    cudaGetSymbolAddress(&pwv, g_wvA);  cudaGetSymbolAddress(&pwo, g_woA);

    EncodeFn enc = nullptr;
    cudaDriverEntryPointQueryResult qres;
    cudaGetDriverEntryPoint("cuTensorMapEncodeTiled", (void**)&enc,
                            cudaEnableDefault, &qres);

    CUtensorMap mQa, mKa, mVa, mAO, mWq, mWk, mWv, mWo;
    make_map(enc, &mQa, pqA, DIMN, MROWS, G_KSTEP, 128);
    make_map(enc, &mKa, pkA, DIMN, MROWS, G_KSTEP, 128);
    make_map(enc, &mVa, pvA, DIMN, MROWS, G_KSTEP, 128);
    make_map(enc, &mAO, pAOh, DIMN, MROWS, G_KSTEP, 128);
    make_map(enc, &mWq, pwq, DIMN, DIMN, G_KSTEP, 256);
    make_map(enc, &mWk, pwk, DIMN, DIMN, G_KSTEP, 256);
    make_map(enc, &mWv, pwv, DIMN, DIMN, G_KSTEP, 256);
    make_map(enc, &mWo, pwo, DIMN, DIMN, G_KSTEP, 256);
    CUtensorMap mAQ, mAK, mAVt;
    make_map(enc, &mAQ,  pQh,  DIMN, MROWS, 64, 128);
    make_map(enc, &mAK,  pKh,  DIMN, MROWS, 64, 64);        // 64-key K tiles
    make_map(enc, &mAVt, pVth, SEQ,  BATCH * DIMN, 64, 64); // 64-key V tiles

    cudaFuncSetAttribute(gemm_qkv_tc, cudaFuncAttributeMaxDynamicSharedMemorySize, G_SMEM_TOTAL);
    cudaFuncSetAttribute(gemm_out_tc, cudaFuncAttributeMaxDynamicSharedMemorySize, G_SMEM_TOTAL);
    cudaFuncSetAttribute(attn_tc,     cudaFuncAttributeMaxDynamicSharedMemorySize, A_TOTAL);

    // prep: fp16 rounding of 7 tensors + mask sniff, one launch
    prep_all<<<dim3(4096, 8), 256>>>(q, k, v, Wq, Wk, Wv, Wo, (const unsigned*)mask);

    // mask bit-pack
    {
        int nw = BATCH * SEQ * MASKW;
        pack_mask<<<(nw + 255) / 256, 256>>>(mask);
    }

    // QKV projections
    gemm_qkv_tc<<<dim3(DIMN / 256, MROWS / 128, 3), 128, G_SMEM_TOTAL>>>(
        mQa, mKa, mVa, mWq, mWk, mWv, bq, bk, bv);

    // fp16 flash attention (64-key tiles, S+P double-buffered, 2 CTAs/SM)
    attn_tc<<<dim3(SEQ / 128, NH, BATCH), 320, A_TOTAL>>>(mAQ, mAK, mAVt);

    // output projection
    gemm_out_tc<<<dim3(DIMN / 256, MROWS / 128), 128, G_SMEM_TOTAL>>>(
        mAO, mWo, bo, (float*)d_out);
}